// round 1
// baseline (speedup 1.0000x reference)
#include <cuda_runtime.h>
#include <cuda_bf16.h>

// out[n,p,d] = feat[n,p,d] * mean_m(task[n,m,p])
// n=32, m=16, p=1024, d=512
// One block per (n,p): warp0 computes the mean over m=16, all 128 threads
// stream d=512 floats as float4.

__global__ __launch_bounds__(128) void MAP_20023137534634_kernel(
    const float* __restrict__ task,   // [32, 16, 1024]
    const float* __restrict__ feat,   // [32, 1024, 512]
    float* __restrict__ out)          // [32, 1024, 512]
{
    const int np = blockIdx.x;        // 0 .. 32*1024-1
    const int n  = np >> 10;
    const int p  = np & 1023;
    const int tid = threadIdx.x;

    __shared__ float s_mean;

    if (tid < 32) {
        float v = 0.0f;
        if (tid < 16) {
            v = task[((size_t)n * 16 + tid) * 1024 + p];
        }
        // reduce 16 lanes
        v += __shfl_xor_sync(0xffffffffu, v, 8);
        v += __shfl_xor_sync(0xffffffffu, v, 4);
        v += __shfl_xor_sync(0xffffffffu, v, 2);
        v += __shfl_xor_sync(0xffffffffu, v, 1);
        if (tid == 0) s_mean = v * (1.0f / 16.0f);
    }
    __syncthreads();

    const float mean = s_mean;

    const size_t base = (size_t)np * 512;
    const float4* __restrict__ f4 = reinterpret_cast<const float4*>(feat + base);
    float4* __restrict__ o4 = reinterpret_cast<float4*>(out + base);

    float4 v = f4[tid];               // 128 threads * 4 floats = 512 = d
    v.x *= mean; v.y *= mean; v.z *= mean; v.w *= mean;
    o4[tid] = v;
}

extern "C" void kernel_launch(void* const* d_in, const int* in_sizes, int n_in,
                              void* d_out, int out_size) {
    const float* task = (const float*)d_in[0];   // 32*16*1024
    const float* feat = (const float*)d_in[1];   // 32*1024*512
    float* out = (float*)d_out;                  // 32*1024*512

    dim3 grid(32 * 1024);
    dim3 block(128);
    MAP_20023137534634_kernel<<<grid, block>>>(task, feat, out);
}

// round 2
// speedup vs baseline: 1.1555x; 1.1555x over previous
#include <cuda_runtime.h>
#include <cuda_bf16.h>

// out[n,p,d] = feat[n,p,d] * mean_m(task[n,m,p])
// n=32, m=16, p=1024, d=512
//
// Two kernels:
//   1) mean_kernel: g_mean[n*1024+p] = mean over m of task[n,m,p]   (32768 floats)
//   2) scale_kernel: pure streaming multiply, 8 independent float4 per thread
//      (front-batched -> MLP 8) with mean via __ldg (L1/L2 broadcast hits).

__device__ float g_mean[32 * 1024];

__global__ __launch_bounds__(256) void mean_kernel(
    const float* __restrict__ task)   // [32, 16, 1024]
{
    const int np = blockIdx.x * 256 + threadIdx.x;   // 0 .. 32767
    const int n  = np >> 10;
    const int p  = np & 1023;

    const float* t = task + (size_t)n * 16 * 1024 + p;
    float s = 0.0f;
#pragma unroll
    for (int m = 0; m < 16; m++) {
        s += t[m * 1024];
    }
    g_mean[np] = s * (1.0f / 16.0f);
}

// total float4 elements: 32*1024*512/4 = 4,194,304
// 2048 blocks * 256 threads * 8 iters = 4,194,304 exactly.
__global__ __launch_bounds__(256) void scale_kernel(
    const float* __restrict__ feat,   // [32, 1024, 512]
    float* __restrict__ out)          // [32, 1024, 512]
{
    const int tid = threadIdx.x;
    const size_t block_base = (size_t)blockIdx.x * 2048;   // float4 units

    const float4* __restrict__ f4 = reinterpret_cast<const float4*>(feat);
    float4* __restrict__ o4 = reinterpret_cast<float4*>(out);

    size_t idx[8];
    float4 v[8];
    float mn[8];

    // front-batch all loads: 8 independent float4 LDG.128 in flight
#pragma unroll
    for (int k = 0; k < 8; k++) {
        idx[k] = block_base + (size_t)k * 256 + tid;
        v[k] = f4[idx[k]];
    }
#pragma unroll
    for (int k = 0; k < 8; k++) {
        // 128 float4 per (n,p) row -> np = idx >> 7; L1/L2 broadcast hit
        mn[k] = __ldg(&g_mean[idx[k] >> 7]);
    }
#pragma unroll
    for (int k = 0; k < 8; k++) {
        v[k].x *= mn[k]; v[k].y *= mn[k]; v[k].z *= mn[k]; v[k].w *= mn[k];
        o4[idx[k]] = v[k];
    }
}

extern "C" void kernel_launch(void* const* d_in, const int* in_sizes, int n_in,
                              void* d_out, int out_size) {
    const float* task = (const float*)d_in[0];   // 32*16*1024
    const float* feat = (const float*)d_in[1];   // 32*1024*512
    float* out = (float*)d_out;                  // 32*1024*512

    mean_kernel<<<128, 256>>>(task);
    scale_kernel<<<2048, 256>>>(feat, out);
}

// round 4
// speedup vs baseline: 1.3954x; 1.2076x over previous
#include <cuda_runtime.h>
#include <cuda_bf16.h>

// out[n,p,d] = feat[n,p,d] * mean_m(task[n,m,p])
// n=32, m=16, p=1024, d=512
//
// Single fused kernel. Each block owns 16 consecutive (n,p) rows
// (16 rows * 128 float4 = 2048 float4 = 32 KB of feat/out).
//   - 8 front-batched float4 feat loads per thread (MLP=8), issued BEFORE
//     the task loads so DRAM latency of feat hides the mean computation.
//   - all 256 threads cooperatively load the 16x16 task slice (coalesced),
//     shfl+smem reduce over m -> 16 row means.
//   - multiply + evict-first stores.

__global__ __launch_bounds__(256) void fused_kernel(
    const float* __restrict__ task,   // [32, 16, 1024]
    const float* __restrict__ feat,   // [32, 1024, 512]
    float* __restrict__ out)          // [32, 1024, 512]
{
    const int tid = threadIdx.x;
    const int bid = blockIdx.x;          // 0..2047
    const int np0 = bid << 4;            // first row of this block
    const int n   = np0 >> 10;
    const int p0  = np0 & 1023;

    __shared__ float s_part[128];        // 8 warps x 16 r-slots
    __shared__ float s_mean[16];

    const size_t block_base = (size_t)bid * 2048;   // in float4 units
    const float4* __restrict__ f4 = reinterpret_cast<const float4*>(feat);
    float4* __restrict__ o4 = reinterpret_cast<float4*>(out);

    // ---- 1) front-batch the 8 independent feat loads (evict-first) ----
    float4 v[8];
#pragma unroll
    for (int k = 0; k < 8; k++) {
        v[k] = __ldcs(&f4[block_base + (size_t)k * 256 + tid]);
    }

    // ---- 2) task mean: thread t loads task[n, m=t>>4, p0 + (t&15)] ----
    {
        const int m = tid >> 4;
        const int r = tid & 15;
        float tv = task[(size_t)n * 16384 + (size_t)m * 1024 + p0 + r];
        // lanes l and l^16 have same r, m differing by 1 -> per-warp pair sum
        tv += __shfl_xor_sync(0xffffffffu, tv, 16);
        const int w = tid >> 5;
        if ((tid & 31) < 16) s_part[w * 16 + r] = tv;
    }
    __syncthreads();
    if (tid < 16) {
        float s = 0.0f;
#pragma unroll
        for (int w = 0; w < 8; w++) s += s_part[w * 16 + tid];
        s_mean[tid] = s * (1.0f / 16.0f);
    }
    __syncthreads();

    // ---- 3) multiply + stream out ----
#pragma unroll
    for (int k = 0; k < 8; k++) {
        const int row_local = (k * 256 + tid) >> 7;   // 0..15
        const float mn = s_mean[row_local];
        float4 x = v[k];
        x.x *= mn; x.y *= mn; x.z *= mn; x.w *= mn;
        __stcs(&o4[block_base + (size_t)k * 256 + tid], x);
    }
}

extern "C" void kernel_launch(void* const* d_in, const int* in_sizes, int n_in,
                              void* d_out, int out_size) {
    const float* task = (const float*)d_in[0];   // 32*16*1024
    const float* feat = (const float*)d_in[1];   // 32*1024*512
    float* out = (float*)d_out;                  // 32*1024*512

    fused_kernel<<<2048, 256>>>(task, feat, out);
}